// round 9
// baseline (speedup 1.0000x reference)
#include <cuda_runtime.h>
#include <cuda_fp16.h>
#include <cstdint>

// STFT via hop-polyphase + one radix-2 DIT level + freq-domain hann.
//   Segment s (512 samples) -> even/odd 256-pt parts:
//     E_k = sum_j x[2j]   e^{-2pi i k j/1024},  O_k likewise (same weights!)
//     U_k = E_k + w^k O_k,  w = e^{-i pi /1024};  k=0..512, conj partner 1024-k
//   GEMM: M=1152 (interleaved cos/-sin rows, k=0..512), K=256, two acc sets
//   (E from x_even, O from x_odd) sharing A fragments. Butterfly in epilogue.
//   Combine: X_t[k] = sum_q (-i)^{kq} U_{t+q}[k]; F = 0.5X - 0.25(X[k-1]+X[k+1])

#define KF     1025
#define NBC    32
#define LEN    262144
#define NT     513
#define NSEG   516
#define NJ     (NBC * NSEG)      // 16512 = 129 * 128
#define MROWSA 1152              // 9 * 128; rows 0..1025 = interleaved (cos,-sin) k=0..512
#define KHALF  256
#define NITER  4                 // KHALF / 64
#define IMAG_OFF 16826400L

__device__ __half g_A[(size_t)MROWSA * KHALF];  // [m][c], m=2k -> cos, 2k+1 -> -sin
__device__ __half g_B[(size_t)NJ * 512];        // [j][c]: c<256 even samples, else odd
__device__ float  g_U[(size_t)2050 * NJ];       // rows 0..1024 re, KF..KF+1024 im
__device__ float  g_cos_tab[2048];
__device__ float  g_msin_tab[2048];

#define SW128(b) ((b) ^ (((b) >> 3) & 0x70))

// ============================ DFT tables ============================
__global__ void init_tab_kernel() {
    int i = blockIdx.x * 256 + threadIdx.x;   // 2048 threads
    float a = (float)i * (1.0f / 1024.0f);
    g_cos_tab[i]  = cospif(a);
    g_msin_tab[i] = -sinpif(a);
}

// ============================ pack A ============================
// row m = 2k+comp, col c: comp 0 -> cos(2pi k c/1024), comp 1 -> -sin(...)
__global__ void pack_a_kernel() {
    int idx2 = (blockIdx.x * 256 + threadIdx.x) * 2;
    int m = idx2 >> 8;
    int c = idx2 & 255;
    __half o[2];
    if (m < 1026) {
        int k = m >> 1;
        const float* tab = (m & 1) ? g_msin_tab : g_cos_tab;
        o[0] = __float2half_rn(tab[(2 * k * c) & 2047]);
        o[1] = __float2half_rn(tab[(2 * k * (c + 1)) & 2047]);
    } else {
        o[0] = o[1] = __float2half_rn(0.f);
    }
    *(__half2*)&g_A[(size_t)m * KHALF + c] = *(__half2*)o;
}

// ============================ pack B (even/odd split) ============================
__global__ void pack_b_kernel(const float* __restrict__ x) {
    int j  = blockIdx.x;
    int bc = j / NSEG;
    int s  = j - bc * NSEG;
    __half* bj = g_B + (size_t)j * 512;
    const float* xbc = x + (size_t)bc * LEN;
    int c = threadIdx.x;            // 0..255
    int pe = s * 512 + 2 * c - 1024;
    int po = pe + 1;
    if (pe < 0) pe = -pe;
    if (pe >= LEN) pe = 2 * LEN - 2 - pe;
    if (po < 0) po = -po;
    if (po >= LEN) po = 2 * LEN - 2 - po;
    bj[c]       = __float2half_rn(xbc[pe]);
    bj[256 + c] = __float2half_rn(xbc[po]);
}

// ============================ GEMM (mma.sync fp16, dual-acc E/O) ============================
#define CP16(dst, src) \
    asm volatile("cp.async.cg.shared.global [%0], [%1], 16;" :: "r"(dst), "l"(src))
#define CP_COMMIT() asm volatile("cp.async.commit_group;" ::: "memory")
#define CP_WAIT1()  asm volatile("cp.async.wait_group 1;" ::: "memory")
#define CP_WAIT0()  asm volatile("cp.async.wait_group 0;" ::: "memory")

__device__ __forceinline__ uint32_t smem_u32(const void* p) {
    uint32_t a;
    asm("{ .reg .u64 t; cvta.to.shared.u64 t, %1; cvt.u32.u64 %0, t; }"
        : "=r"(a) : "l"(p));
    return a;
}
__device__ __forceinline__ void ldsm4(uint32_t* r, uint32_t addr) {
    asm volatile("ldmatrix.sync.aligned.m8n8.x4.shared.b16 {%0,%1,%2,%3}, [%4];"
                 : "=r"(r[0]), "=r"(r[1]), "=r"(r[2]), "=r"(r[3]) : "r"(addr));
}
__device__ __forceinline__ void mma16816(float* d, const uint32_t* a, const uint32_t* b) {
    asm volatile(
        "mma.sync.aligned.m16n8k16.row.col.f32.f16.f16.f32 "
        "{%0,%1,%2,%3},{%4,%5,%6,%7},{%8,%9},{%0,%1,%2,%3};"
        : "+f"(d[0]), "+f"(d[1]), "+f"(d[2]), "+f"(d[3])
        : "r"(a[0]), "r"(a[1]), "r"(a[2]), "r"(a[3]), "r"(b[0]), "r"(b[1]));
}

#define TILE_BYTES 16384              // 128 rows x 128B (64 fp16)
#define STAGE_BYTES (3 * TILE_BYTES)  // A, BE, BO
#define GEMM_SMEM  (3 * STAGE_BYTES)  // 3-stage ring (147456 B); epilogue reuses it

__global__ void __launch_bounds__(256) gemm_mma_kernel() {
    extern __shared__ char smem[];
    const int tid = threadIdx.x;
    const int wid = tid >> 5;        // 0..7
    const int lane = tid & 31;
    const int m0 = blockIdx.y * 128;
    const int j0 = blockIdx.x * 128;

    const uint32_t sbase = smem_u32(smem);

    // ---- loader: row = tid>>1, 64B half-row = tid&1, 4 x 16B each ----
    const int lrow = tid >> 1;
    const int half = tid & 1;
    const __half* gA  = g_A + (size_t)(m0 + lrow) * KHALF + half * 32;
    const __half* gBe = g_B + (size_t)(j0 + lrow) * 512 + half * 32;
    const __half* gBo = gBe + 256;
    uint32_t soff[4];
#pragma unroll
    for (int q = 0; q < 4; ++q)
        soff[q] = SW128((uint32_t)lrow * 128 + half * 64 + q * 16);

#define ISSUE_LOAD(it, buf) do {                                               \
    uint32_t _b = sbase + (buf) * STAGE_BYTES;                                 \
    const __half* _ga = gA  + (it) * 64;                                       \
    const __half* _ge = gBe + (it) * 64;                                       \
    const __half* _go = gBo + (it) * 64;                                       \
    _Pragma("unroll")                                                          \
    for (int q = 0; q < 4; ++q) {                                              \
        CP16(_b + soff[q],                  _ga + q * 8);                      \
        CP16(_b + TILE_BYTES + soff[q],     _ge + q * 8);                      \
        CP16(_b + 2 * TILE_BYTES + soff[q], _go + q * 8);                      \
    }                                                                          \
} while (0)

    // ---- warp grid 4x2: warp tile 32(m) x 64(j) ----
    const int wm = wid >> 1;         // 0..3
    const int wn = wid & 1;          // 0..1
    const int arow = wm * 32 + (lane & 15);
    const int abyt = (lane >> 4) * 16;
    const int brow = wn * 64 + ((lane >> 4) << 3) + (lane & 7);
    const int bbyt = ((lane >> 3) & 1) * 16;

    float accE[2][8][4], accO[2][8][4];
#pragma unroll
    for (int i = 0; i < 2; ++i)
#pragma unroll
        for (int jt = 0; jt < 8; ++jt)
#pragma unroll
            for (int e = 0; e < 4; ++e) { accE[i][jt][e] = 0.f; accO[i][jt][e] = 0.f; }

    ISSUE_LOAD(0, 0); CP_COMMIT();
    ISSUE_LOAD(1, 1); CP_COMMIT();

    for (int it = 0; it < NITER; ++it) {
        if (it < NITER - 1) CP_WAIT1(); else CP_WAIT0();
        __syncthreads();
        if (it + 2 < NITER) { ISSUE_LOAD(it + 2, (it + 2) % 3); CP_COMMIT(); }

        const uint32_t bA = sbase + (it % 3) * STAGE_BYTES;
        const uint32_t bE = bA + TILE_BYTES;
        const uint32_t bO = bA + 2 * TILE_BYTES;
#pragma unroll
        for (int s = 0; s < 4; ++s) {
            uint32_t a[2][4], be[4][4], bo[4][4];
#pragma unroll
            for (int i = 0; i < 2; ++i)
                ldsm4(a[i], bA + SW128((uint32_t)(arow + i * 16) * 128 + s * 32 + abyt));
#pragma unroll
            for (int p = 0; p < 4; ++p) {
                ldsm4(be[p], bE + SW128((uint32_t)(brow + p * 16) * 128 + s * 32 + bbyt));
                ldsm4(bo[p], bO + SW128((uint32_t)(brow + p * 16) * 128 + s * 32 + bbyt));
            }
#pragma unroll
            for (int i = 0; i < 2; ++i) {
#pragma unroll
                for (int p = 0; p < 4; ++p) {
                    mma16816(accE[i][2 * p],     a[i], &be[p][0]);
                    mma16816(accE[i][2 * p + 1], a[i], &be[p][2]);
                    mma16816(accO[i][2 * p],     a[i], &bo[p][0]);
                    mma16816(accO[i][2 * p + 1], a[i], &bo[p][2]);
                }
            }
        }
    }

    // ---- epilogue: stage E,O to smem, butterfly, write U (and conj partner) ----
    __syncthreads();
    float* smE = (float*)smem;               // [128][132]
    float* smO = smE + 128 * 132;            // 2*128*132*4 = 135168 <= 147456
    {
        const int r0 = wm * 32 + (lane >> 2);
        const int c0 = wn * 64 + (lane & 3) * 2;
#pragma unroll
        for (int i = 0; i < 2; ++i) {
#pragma unroll
            for (int jt = 0; jt < 8; ++jt) {
                int r = r0 + i * 16;
                int c = c0 + jt * 8;
                smE[r * 132 + c]       = accE[i][jt][0];
                smE[r * 132 + c + 1]   = accE[i][jt][1];
                smE[(r + 8) * 132 + c]     = accE[i][jt][2];
                smE[(r + 8) * 132 + c + 1] = accE[i][jt][3];
                smO[r * 132 + c]       = accO[i][jt][0];
                smO[r * 132 + c + 1]   = accO[i][jt][1];
                smO[(r + 8) * 132 + c]     = accO[i][jt][2];
                smO[(r + 8) * 132 + c + 1] = accO[i][jt][3];
            }
        }
    }
    __syncthreads();

    const int jl = tid & 127;                // j within tile (coalesced)
    const int kh = tid >> 7;                 // 0..1
    const size_t jg = (size_t)j0 + jl;
#pragma unroll 4
    for (int h = 0; h < 32; ++h) {
        int kloc = kh + h * 2;               // 0..63
        int kg = (m0 >> 1) + kloc;
        if (kg > 512) break;                 // uniform across block halves? kh differs -> per-thread
        float er = smE[(2 * kloc) * 132 + jl];
        float ei = smE[(2 * kloc + 1) * 132 + jl];
        float or_ = smO[(2 * kloc) * 132 + jl];
        float oi = smO[(2 * kloc + 1) * 132 + jl];
        float cw = g_cos_tab[kg];
        float sw = g_msin_tab[kg];
        float pr = cw * or_ - sw * oi;
        float pi = cw * oi + sw * or_;
        // U_k
        g_U[(size_t)kg * NJ + jg]        = er + pr;
        g_U[(size_t)(KF + kg) * NJ + jg] = ei + pi;
        // U_{1024-k} (k=512 duplicates identically)
        int k2 = 1024 - kg;
        g_U[(size_t)k2 * NJ + jg]        = er - pr;
        g_U[(size_t)(KF + k2) * NJ + jg] = -(ei - pi);
    }
}

// ============================ combine (t-vectorized, smem re-coalesce) ============================
__global__ void __launch_bounds__(128) combine5_kernel(float* __restrict__ out) {
    __shared__ float sfr[4][2][128];
    __shared__ float sfi[4][2][128];
    const int bc   = blockIdx.z;
    const int lane = threadIdx.x;        // 0..31
    const int ty   = threadIdx.y;        // 0..3
    const int tbase = blockIdx.x * 128;
    const int kb   = (blockIdx.y * 4 + ty) * 32;
    if (kb > 1024) return;

    const int t4  = tbase + lane * 4;
    const int tt4 = (t4 <= 512) ? t4 : 512;
    const size_t jj = (size_t)bc * NSEG + tt4;
    const long baseT = (long)bc * KF;

    float pXr0[4], pXr1[4], pXi0[4], pXi1[4];
#pragma unroll
    for (int e = 0; e < 4; ++e) { pXr0[e] = pXr1[e] = pXi0[e] = pXi1[e] = 0.f; }

#pragma unroll 2
    for (int i = 0; i < 34; ++i) {
        int k = kb - 1 + i;
        int kk = k;
        float sgn = 1.f;
        if (kk < 0)         { kk = -kk;       sgn = -1.f; }
        else if (kk > 1024) { kk = 2048 - kk; sgn = -1.f; }

        const float4* ur4 = (const float4*)(g_U + (size_t)kk * NJ + jj);
        const float4* ui4 = (const float4*)(g_U + (size_t)(KF + kk) * NJ + jj);
        float4 rlo = ur4[0], rhi = ur4[1];
        float4 ilo = ui4[0], ihi = ui4[1];
        float rr[8] = {rlo.x, rlo.y, rlo.z, rlo.w, rhi.x, rhi.y, rhi.z, rhi.w};
        float ii[8] = {ilo.x, ilo.y, ilo.z, ilo.w, ihi.x, ihi.y, ihi.z, ihi.w};

        float xr[4], xi[4];
        switch (kk & 3) {
            case 0:
#pragma unroll
                for (int e = 0; e < 4; ++e) {
                    xr[e] = rr[e] + rr[e+1] + rr[e+2] + rr[e+3];
                    xi[e] = sgn * (ii[e] + ii[e+1] + ii[e+2] + ii[e+3]);
                }
                break;
            case 1:
#pragma unroll
                for (int e = 0; e < 4; ++e) {
                    xr[e] = rr[e] + ii[e+1] - rr[e+2] - ii[e+3];
                    xi[e] = sgn * (ii[e] - rr[e+1] - ii[e+2] + rr[e+3]);
                }
                break;
            case 2:
#pragma unroll
                for (int e = 0; e < 4; ++e) {
                    xr[e] = rr[e] - rr[e+1] + rr[e+2] - rr[e+3];
                    xi[e] = sgn * (ii[e] - ii[e+1] + ii[e+2] - ii[e+3]);
                }
                break;
            default:
#pragma unroll
                for (int e = 0; e < 4; ++e) {
                    xr[e] = rr[e] - ii[e+1] - rr[e+2] + ii[e+3];
                    xi[e] = sgn * (ii[e] + rr[e+1] - ii[e+2] - rr[e+3]);
                }
                break;
        }

        if (i >= 2) {
            const int ko = k - 1;
            const int buf = i & 1;
            float4 vr, vi;
            vr.x = 0.5f * pXr1[0] - 0.25f * (pXr0[0] + xr[0]);
            vr.y = 0.5f * pXr1[1] - 0.25f * (pXr0[1] + xr[1]);
            vr.z = 0.5f * pXr1[2] - 0.25f * (pXr0[2] + xr[2]);
            vr.w = 0.5f * pXr1[3] - 0.25f * (pXr0[3] + xr[3]);
            vi.x = 0.5f * pXi1[0] - 0.25f * (pXi0[0] + xi[0]);
            vi.y = 0.5f * pXi1[1] - 0.25f * (pXi0[1] + xi[1]);
            vi.z = 0.5f * pXi1[2] - 0.25f * (pXi0[2] + xi[2]);
            vi.w = 0.5f * pXi1[3] - 0.25f * (pXi0[3] + xi[3]);
            *(float4*)&sfr[ty][buf][lane * 4] = vr;
            *(float4*)&sfi[ty][buf][lane * 4] = vi;
            __syncwarp();
            if (ko <= 1024) {
                const long baseR = (baseT + ko) * NT;
#pragma unroll
                for (int e = 0; e < 4; ++e) {
                    int t = tbase + 32 * e + lane;
                    if (t <= 512) {
                        out[baseR + t]            = sfr[ty][buf][32 * e + lane];
                        out[IMAG_OFF + baseR + t] = sfi[ty][buf][32 * e + lane];
                    }
                }
            }
        }
#pragma unroll
        for (int e = 0; e < 4; ++e) {
            pXr0[e] = pXr1[e]; pXr1[e] = xr[e];
            pXi0[e] = pXi1[e]; pXi1[e] = xi[e];
        }
    }
}

// ============================ launch ============================
extern "C" void kernel_launch(void* const* d_in, const int* in_sizes, int n_in,
                              void* d_out, int out_size)
{
    const float* x = (const float*)d_in[0];
    float* out = (float*)d_out;

    cudaFuncSetAttribute(gemm_mma_kernel,
                         cudaFuncAttributeMaxDynamicSharedMemorySize, GEMM_SMEM);

    init_tab_kernel<<<8, 256>>>();
    pack_a_kernel<<<(MROWSA * KHALF) / 512, 256>>>();
    pack_b_kernel<<<NJ, 256>>>(x);
    gemm_mma_kernel<<<dim3(NJ / 128, MROWSA / 128), 256, GEMM_SMEM>>>();
    combine5_kernel<<<dim3(5, 9, NBC), dim3(32, 4)>>>(out);
}

// round 10
// speedup vs baseline: 1.1277x; 1.1277x over previous
#include <cuda_runtime.h>
#include <cuda_fp16.h>
#include <cstdint>

// STFT via hop-polyphase + one radix-2 DIT level + freq-domain hann.
//   E_k, O_k = 256-pt DFTs (1024-periodic) of even/odd samples, same weights.
//   U_k = E_k + w^k O_k (w^k = e^{-i pi k/1024}), k=0..512; U_{1024-k} = conj(E_k - w^k O_k).
//   GEMM: M=1152 (interleaved cos/-sin, k=0..512), K=256, dual acc (E,O).
//   U stored as fp16. Combine: X_t[k] = sum_q (-i)^{kq} U_{t+q}[k];
//   F = 0.5X[k] - 0.25(X[k-1]+X[k+1]).

#define KF     1025
#define NBC    32
#define LEN    262144
#define NT     513
#define NSEG   516
#define NJ     (NBC * NSEG)      // 16512
#define MROWSA 1152              // 9 * 128
#define KHALF  256
#define NITER  4                 // KHALF / 64
#define IMAG_OFF 16826400L

__device__ __half g_A[(size_t)MROWSA * KHALF];
__device__ __half g_B[(size_t)NJ * 512];        // [j][c]: c<256 even, else odd
__device__ __half g_Uh[(size_t)2050 * NJ + 32]; // rows 0..1024 re, 1025..2049 im (+pad)
__device__ float  g_cos_tab[2048];
__device__ float  g_msin_tab[2048];

#define SW128(b) ((b) ^ (((b) >> 3) & 0x70))

// ============================ DFT tables ============================
__global__ void init_tab_kernel() {
    int i = blockIdx.x * 256 + threadIdx.x;
    float a = (float)i * (1.0f / 1024.0f);
    g_cos_tab[i]  = cospif(a);
    g_msin_tab[i] = -sinpif(a);
}

// ============================ pack A ============================
__global__ void pack_a_kernel() {
    int idx2 = (blockIdx.x * 256 + threadIdx.x) * 2;
    int m = idx2 >> 8;
    int c = idx2 & 255;
    __half o[2];
    if (m < 1026) {
        int k = m >> 1;
        const float* tab = (m & 1) ? g_msin_tab : g_cos_tab;
        o[0] = __float2half_rn(tab[(2 * k * c) & 2047]);
        o[1] = __float2half_rn(tab[(2 * k * (c + 1)) & 2047]);
    } else {
        o[0] = o[1] = __float2half_rn(0.f);
    }
    *(__half2*)&g_A[(size_t)m * KHALF + c] = *(__half2*)o;
}

// ============================ pack B (even/odd split) ============================
__global__ void pack_b_kernel(const float* __restrict__ x) {
    int j  = blockIdx.x;
    int bc = j / NSEG;
    int s  = j - bc * NSEG;
    __half* bj = g_B + (size_t)j * 512;
    const float* xbc = x + (size_t)bc * LEN;
    int c = threadIdx.x;            // 0..255
    int pe = s * 512 + 2 * c - 1024;
    int po = pe + 1;
    if (pe < 0) pe = -pe;
    if (pe >= LEN) pe = 2 * LEN - 2 - pe;
    if (po < 0) po = -po;
    if (po >= LEN) po = 2 * LEN - 2 - po;
    bj[c]       = __float2half_rn(xbc[pe]);
    bj[256 + c] = __float2half_rn(xbc[po]);
}

// ============================ GEMM (mma.sync fp16, dual-acc E/O) ============================
#define CP16(dst, src) \
    asm volatile("cp.async.cg.shared.global [%0], [%1], 16;" :: "r"(dst), "l"(src))
#define CP_COMMIT() asm volatile("cp.async.commit_group;" ::: "memory")
#define CP_WAIT1()  asm volatile("cp.async.wait_group 1;" ::: "memory")
#define CP_WAIT0()  asm volatile("cp.async.wait_group 0;" ::: "memory")

__device__ __forceinline__ uint32_t smem_u32(const void* p) {
    uint32_t a;
    asm("{ .reg .u64 t; cvta.to.shared.u64 t, %1; cvt.u32.u64 %0, t; }"
        : "=r"(a) : "l"(p));
    return a;
}
__device__ __forceinline__ void ldsm4(uint32_t* r, uint32_t addr) {
    asm volatile("ldmatrix.sync.aligned.m8n8.x4.shared.b16 {%0,%1,%2,%3}, [%4];"
                 : "=r"(r[0]), "=r"(r[1]), "=r"(r[2]), "=r"(r[3]) : "r"(addr));
}
__device__ __forceinline__ void mma16816(float* d, const uint32_t* a, const uint32_t* b) {
    asm volatile(
        "mma.sync.aligned.m16n8k16.row.col.f32.f16.f16.f32 "
        "{%0,%1,%2,%3},{%4,%5,%6,%7},{%8,%9},{%0,%1,%2,%3};"
        : "+f"(d[0]), "+f"(d[1]), "+f"(d[2]), "+f"(d[3])
        : "r"(a[0]), "r"(a[1]), "r"(a[2]), "r"(a[3]), "r"(b[0]), "r"(b[1]));
}

#define TILE_BYTES 16384
#define STAGE_BYTES (3 * TILE_BYTES)  // A, BE, BO
#define GEMM_SMEM  (3 * STAGE_BYTES)  // 147456; epilogue reuses (needs 135168)

__global__ void __launch_bounds__(256) gemm_mma_kernel() {
    extern __shared__ char smem[];
    const int tid = threadIdx.x;
    const int wid = tid >> 5;
    const int lane = tid & 31;
    const int m0 = blockIdx.y * 128;
    const int j0 = blockIdx.x * 128;

    const uint32_t sbase = smem_u32(smem);

    const int lrow = tid >> 1;
    const int half = tid & 1;
    const __half* gA  = g_A + (size_t)(m0 + lrow) * KHALF + half * 32;
    const __half* gBe = g_B + (size_t)(j0 + lrow) * 512 + half * 32;
    const __half* gBo = gBe + 256;
    uint32_t soff[4];
#pragma unroll
    for (int q = 0; q < 4; ++q)
        soff[q] = SW128((uint32_t)lrow * 128 + half * 64 + q * 16);

#define ISSUE_LOAD(it, buf) do {                                               \
    uint32_t _b = sbase + (buf) * STAGE_BYTES;                                 \
    const __half* _ga = gA  + (it) * 64;                                       \
    const __half* _ge = gBe + (it) * 64;                                       \
    const __half* _go = gBo + (it) * 64;                                       \
    _Pragma("unroll")                                                          \
    for (int q = 0; q < 4; ++q) {                                              \
        CP16(_b + soff[q],                  _ga + q * 8);                      \
        CP16(_b + TILE_BYTES + soff[q],     _ge + q * 8);                      \
        CP16(_b + 2 * TILE_BYTES + soff[q], _go + q * 8);                      \
    }                                                                          \
} while (0)

    const int wm = wid >> 1;
    const int wn = wid & 1;
    const int arow = wm * 32 + (lane & 15);
    const int abyt = (lane >> 4) * 16;
    const int brow = wn * 64 + ((lane >> 4) << 3) + (lane & 7);
    const int bbyt = ((lane >> 3) & 1) * 16;

    float accE[2][8][4], accO[2][8][4];
#pragma unroll
    for (int i = 0; i < 2; ++i)
#pragma unroll
        for (int jt = 0; jt < 8; ++jt)
#pragma unroll
            for (int e = 0; e < 4; ++e) { accE[i][jt][e] = 0.f; accO[i][jt][e] = 0.f; }

    ISSUE_LOAD(0, 0); CP_COMMIT();
    ISSUE_LOAD(1, 1); CP_COMMIT();

    for (int it = 0; it < NITER; ++it) {
        if (it < NITER - 1) CP_WAIT1(); else CP_WAIT0();
        __syncthreads();
        if (it + 2 < NITER) { ISSUE_LOAD(it + 2, (it + 2) % 3); CP_COMMIT(); }

        const uint32_t bA = sbase + (it % 3) * STAGE_BYTES;
        const uint32_t bE = bA + TILE_BYTES;
        const uint32_t bO = bA + 2 * TILE_BYTES;
#pragma unroll
        for (int s = 0; s < 4; ++s) {
            uint32_t a[2][4], be[4][4], bo[4][4];
#pragma unroll
            for (int i = 0; i < 2; ++i)
                ldsm4(a[i], bA + SW128((uint32_t)(arow + i * 16) * 128 + s * 32 + abyt));
#pragma unroll
            for (int p = 0; p < 4; ++p) {
                ldsm4(be[p], bE + SW128((uint32_t)(brow + p * 16) * 128 + s * 32 + bbyt));
                ldsm4(bo[p], bO + SW128((uint32_t)(brow + p * 16) * 128 + s * 32 + bbyt));
            }
#pragma unroll
            for (int i = 0; i < 2; ++i) {
#pragma unroll
                for (int p = 0; p < 4; ++p) {
                    mma16816(accE[i][2 * p],     a[i], &be[p][0]);
                    mma16816(accE[i][2 * p + 1], a[i], &be[p][2]);
                    mma16816(accO[i][2 * p],     a[i], &bo[p][0]);
                    mma16816(accO[i][2 * p + 1], a[i], &bo[p][2]);
                }
            }
        }
    }

    // ---- epilogue: stage E,O to smem, butterfly, half stores ----
    __syncthreads();
    float* smE = (float*)smem;               // [128][132]
    float* smO = smE + 128 * 132;
    {
        const int r0 = wm * 32 + (lane >> 2);
        const int c0 = wn * 64 + (lane & 3) * 2;
#pragma unroll
        for (int i = 0; i < 2; ++i) {
#pragma unroll
            for (int jt = 0; jt < 8; ++jt) {
                int r = r0 + i * 16;
                int c = c0 + jt * 8;
                smE[r * 132 + c]           = accE[i][jt][0];
                smE[r * 132 + c + 1]       = accE[i][jt][1];
                smE[(r + 8) * 132 + c]     = accE[i][jt][2];
                smE[(r + 8) * 132 + c + 1] = accE[i][jt][3];
                smO[r * 132 + c]           = accO[i][jt][0];
                smO[r * 132 + c + 1]       = accO[i][jt][1];
                smO[(r + 8) * 132 + c]     = accO[i][jt][2];
                smO[(r + 8) * 132 + c + 1] = accO[i][jt][3];
            }
        }
    }
    __syncthreads();

    // warp wid -> k's 8*wid..8*wid+7 (local); lane -> 4 j's. Vector LDS/STG.
    const int jl = lane * 4;
    const size_t jg = (size_t)j0 + jl;
#pragma unroll
    for (int h = 0; h < 8; ++h) {
        int kloc = wid * 8 + h;              // 0..63
        int kg = (m0 >> 1) + kloc;
        if (kg > 512) break;                 // warp-uniform
        float4 er = *(float4*)&smE[(2 * kloc) * 132 + jl];
        float4 ei = *(float4*)&smE[(2 * kloc + 1) * 132 + jl];
        float4 o_r = *(float4*)&smO[(2 * kloc) * 132 + jl];
        float4 oi = *(float4*)&smO[(2 * kloc + 1) * 132 + jl];
        float cw = g_cos_tab[kg];
        float sw = g_msin_tab[kg];

        float prx = cw * o_r.x - sw * oi.x, pix = cw * oi.x + sw * o_r.x;
        float pry = cw * o_r.y - sw * oi.y, piy = cw * oi.y + sw * o_r.y;
        float prz = cw * o_r.z - sw * oi.z, piz = cw * oi.z + sw * o_r.z;
        float prw = cw * o_r.w - sw * oi.w, piw = cw * oi.w + sw * o_r.w;

        __half2 ur_lo = __floats2half2_rn(er.x + prx, er.y + pry);
        __half2 ur_hi = __floats2half2_rn(er.z + prz, er.w + prw);
        __half2 ui_lo = __floats2half2_rn(ei.x + pix, ei.y + piy);
        __half2 ui_hi = __floats2half2_rn(ei.z + piz, ei.w + piw);
        __half2 vr_lo = __floats2half2_rn(er.x - prx, er.y - pry);
        __half2 vr_hi = __floats2half2_rn(er.z - prz, er.w - prw);
        __half2 vi_lo = __floats2half2_rn(pix - ei.x, piy - ei.y);
        __half2 vi_hi = __floats2half2_rn(piz - ei.z, piw - ei.w);

        int k2 = 1024 - kg;
        *(__half2*)(g_Uh + (size_t)kg * NJ + jg)              = ur_lo;
        *(__half2*)(g_Uh + (size_t)kg * NJ + jg + 2)          = ur_hi;
        *(__half2*)(g_Uh + (size_t)(KF + kg) * NJ + jg)       = ui_lo;
        *(__half2*)(g_Uh + (size_t)(KF + kg) * NJ + jg + 2)   = ui_hi;
        *(__half2*)(g_Uh + (size_t)k2 * NJ + jg)              = vr_lo;
        *(__half2*)(g_Uh + (size_t)k2 * NJ + jg + 2)          = vr_hi;
        *(__half2*)(g_Uh + (size_t)(KF + k2) * NJ + jg)       = vi_lo;
        *(__half2*)(g_Uh + (size_t)(KF + k2) * NJ + jg + 2)   = vi_hi;
    }
}

// ============================ combine (half U, t-vectorized) ============================
__device__ __forceinline__ void load8h(const __half* p, float* dst) {
    uint2 v0 = *(const uint2*)p;
    uint2 v1 = *(const uint2*)(p + 4);
    __half2* h = (__half2*)&v0;
    float2 f;
    f = __half22float2(h[0]); dst[0] = f.x; dst[1] = f.y;
    f = __half22float2(h[1]); dst[2] = f.x; dst[3] = f.y;
    h = (__half2*)&v1;
    f = __half22float2(h[0]); dst[4] = f.x; dst[5] = f.y;
    f = __half22float2(h[1]); dst[6] = f.x; dst[7] = f.y;
}

__global__ void __launch_bounds__(128) combine5_kernel(float* __restrict__ out) {
    __shared__ float sfr[4][2][128];
    __shared__ float sfi[4][2][128];
    const int bc   = blockIdx.z;
    const int lane = threadIdx.x;
    const int ty   = threadIdx.y;
    const int tbase = blockIdx.x * 128;
    const int kb   = (blockIdx.y * 4 + ty) * 32;
    if (kb > 1024) return;

    const int t4  = tbase + lane * 4;
    const int tt4 = (t4 <= 512) ? t4 : 512;
    const size_t jj = (size_t)bc * NSEG + tt4;
    const long baseT = (long)bc * KF;

    float pXr0[4], pXr1[4], pXi0[4], pXi1[4];
#pragma unroll
    for (int e = 0; e < 4; ++e) { pXr0[e] = pXr1[e] = pXi0[e] = pXi1[e] = 0.f; }

#pragma unroll 2
    for (int i = 0; i < 34; ++i) {
        int k = kb - 1 + i;
        int kk = k;
        float sgn = 1.f;
        if (kk < 0)         { kk = -kk;       sgn = -1.f; }
        else if (kk > 1024) { kk = 2048 - kk; sgn = -1.f; }

        float rr[8], ii[8];
        load8h(g_Uh + (size_t)kk * NJ + jj, rr);
        load8h(g_Uh + (size_t)(KF + kk) * NJ + jj, ii);

        float xr[4], xi[4];
        switch (kk & 3) {
            case 0:
#pragma unroll
                for (int e = 0; e < 4; ++e) {
                    xr[e] = rr[e] + rr[e+1] + rr[e+2] + rr[e+3];
                    xi[e] = sgn * (ii[e] + ii[e+1] + ii[e+2] + ii[e+3]);
                }
                break;
            case 1:
#pragma unroll
                for (int e = 0; e < 4; ++e) {
                    xr[e] = rr[e] + ii[e+1] - rr[e+2] - ii[e+3];
                    xi[e] = sgn * (ii[e] - rr[e+1] - ii[e+2] + rr[e+3]);
                }
                break;
            case 2:
#pragma unroll
                for (int e = 0; e < 4; ++e) {
                    xr[e] = rr[e] - rr[e+1] + rr[e+2] - rr[e+3];
                    xi[e] = sgn * (ii[e] - ii[e+1] + ii[e+2] - ii[e+3]);
                }
                break;
            default:
#pragma unroll
                for (int e = 0; e < 4; ++e) {
                    xr[e] = rr[e] - ii[e+1] - rr[e+2] + ii[e+3];
                    xi[e] = sgn * (ii[e] + rr[e+1] - ii[e+2] - rr[e+3]);
                }
                break;
        }

        if (i >= 2) {
            const int ko = k - 1;
            const int buf = i & 1;
            float4 vr, vi;
            vr.x = 0.5f * pXr1[0] - 0.25f * (pXr0[0] + xr[0]);
            vr.y = 0.5f * pXr1[1] - 0.25f * (pXr0[1] + xr[1]);
            vr.z = 0.5f * pXr1[2] - 0.25f * (pXr0[2] + xr[2]);
            vr.w = 0.5f * pXr1[3] - 0.25f * (pXr0[3] + xr[3]);
            vi.x = 0.5f * pXi1[0] - 0.25f * (pXi0[0] + xi[0]);
            vi.y = 0.5f * pXi1[1] - 0.25f * (pXi0[1] + xi[1]);
            vi.z = 0.5f * pXi1[2] - 0.25f * (pXi0[2] + xi[2]);
            vi.w = 0.5f * pXi1[3] - 0.25f * (pXi0[3] + xi[3]);
            *(float4*)&sfr[ty][buf][lane * 4] = vr;
            *(float4*)&sfi[ty][buf][lane * 4] = vi;
            __syncwarp();
            if (ko <= 1024) {
                const long baseR = (baseT + ko) * NT;
#pragma unroll
                for (int e = 0; e < 4; ++e) {
                    int t = tbase + 32 * e + lane;
                    if (t <= 512) {
                        out[baseR + t]            = sfr[ty][buf][32 * e + lane];
                        out[IMAG_OFF + baseR + t] = sfi[ty][buf][32 * e + lane];
                    }
                }
            }
        }
#pragma unroll
        for (int e = 0; e < 4; ++e) {
            pXr0[e] = pXr1[e]; pXr1[e] = xr[e];
            pXi0[e] = pXi1[e]; pXi1[e] = xi[e];
        }
    }
}

// ============================ launch ============================
extern "C" void kernel_launch(void* const* d_in, const int* in_sizes, int n_in,
                              void* d_out, int out_size)
{
    const float* x = (const float*)d_in[0];
    float* out = (float*)d_out;

    cudaFuncSetAttribute(gemm_mma_kernel,
                         cudaFuncAttributeMaxDynamicSharedMemorySize, GEMM_SMEM);

    init_tab_kernel<<<8, 256>>>();
    pack_a_kernel<<<(MROWSA * KHALF) / 512, 256>>>();
    pack_b_kernel<<<NJ, 256>>>(x);
    gemm_mma_kernel<<<dim3(NJ / 128, MROWSA / 128), 256, GEMM_SMEM>>>();
    combine5_kernel<<<dim3(5, 9, NBC), dim3(32, 4)>>>(out);
}

// round 11
// speedup vs baseline: 1.2982x; 1.1512x over previous
#include <cuda_runtime.h>
#include <cuda_fp16.h>
#include <cstdint>

// STFT via hop-polyphase + one radix-2 DIT level + freq-domain hann.
//   E_k, O_k = 256-pt DFTs (1024-periodic) of even/odd samples, same weights.
//   U_k = E_k + w^k O_k, k=0..512; U_{1024-k} = conj(E_k - w^k O_k).
//   GEMM: CTA tile 64m x 128j (kg-strip of 32), K=256, dual acc (E,O).
//   U stored fp16. Combine: X_t[k] = sum_q (-i)^{kq} U_{t+q}[k];
//   F = 0.5X[k] - 0.25(X[k-1]+X[k+1]).

#define KF     1025
#define NBC    32
#define LEN    262144
#define NT     513
#define NSEG   516
#define NJ     (NBC * NSEG)      // 16512
#define MROWSA 1152
#define KHALF  256
#define NITER  4                 // KHALF / 64
#define IMAG_OFF 16826400L

__device__ __half g_A[(size_t)MROWSA * KHALF];
__device__ __half g_B[(size_t)NJ * 512];        // [j][c]: c<256 even, else odd
__device__ __half g_Uh[(size_t)2050 * NJ + 32]; // rows 0..1024 re, 1025..2049 im
__device__ float  g_cos_tab[2048];
__device__ float  g_msin_tab[2048];

#define SW128(b) ((b) ^ (((b) >> 3) & 0x70))

// ============================ DFT tables ============================
__global__ void init_tab_kernel() {
    int i = blockIdx.x * 256 + threadIdx.x;
    float a = (float)i * (1.0f / 1024.0f);
    g_cos_tab[i]  = cospif(a);
    g_msin_tab[i] = -sinpif(a);
}

// ============================ pack A ============================
__global__ void pack_a_kernel() {
    int idx2 = (blockIdx.x * 256 + threadIdx.x) * 2;
    int m = idx2 >> 8;
    int c = idx2 & 255;
    __half o[2];
    if (m < 1026) {
        int k = m >> 1;
        const float* tab = (m & 1) ? g_msin_tab : g_cos_tab;
        o[0] = __float2half_rn(tab[(2 * k * c) & 2047]);
        o[1] = __float2half_rn(tab[(2 * k * (c + 1)) & 2047]);
    } else {
        o[0] = o[1] = __float2half_rn(0.f);
    }
    *(__half2*)&g_A[(size_t)m * KHALF + c] = *(__half2*)o;
}

// ============================ pack B (even/odd split) ============================
__global__ void pack_b_kernel(const float* __restrict__ x) {
    int j  = blockIdx.x;
    int bc = j / NSEG;
    int s  = j - bc * NSEG;
    __half* bj = g_B + (size_t)j * 512;
    const float* xbc = x + (size_t)bc * LEN;
    int c = threadIdx.x;            // 0..255
    int pe = s * 512 + 2 * c - 1024;
    int po = pe + 1;
    if (pe < 0) pe = -pe;
    if (pe >= LEN) pe = 2 * LEN - 2 - pe;
    if (po < 0) po = -po;
    if (po >= LEN) po = 2 * LEN - 2 - po;
    bj[c]       = __float2half_rn(xbc[pe]);
    bj[256 + c] = __float2half_rn(xbc[po]);
}

// ============================ GEMM (mma.sync fp16, dual-acc E/O) ============================
#define CP16(dst, src) \
    asm volatile("cp.async.cg.shared.global [%0], [%1], 16;" :: "r"(dst), "l"(src))
#define CP_COMMIT() asm volatile("cp.async.commit_group;" ::: "memory")
#define CP_WAIT1()  asm volatile("cp.async.wait_group 1;" ::: "memory")
#define CP_WAIT0()  asm volatile("cp.async.wait_group 0;" ::: "memory")

__device__ __forceinline__ uint32_t smem_u32(const void* p) {
    uint32_t a;
    asm("{ .reg .u64 t; cvta.to.shared.u64 t, %1; cvt.u32.u64 %0, t; }"
        : "=r"(a) : "l"(p));
    return a;
}
__device__ __forceinline__ void ldsm4(uint32_t* r, uint32_t addr) {
    asm volatile("ldmatrix.sync.aligned.m8n8.x4.shared.b16 {%0,%1,%2,%3}, [%4];"
                 : "=r"(r[0]), "=r"(r[1]), "=r"(r[2]), "=r"(r[3]) : "r"(addr));
}
__device__ __forceinline__ void mma16816(float* d, const uint32_t* a, const uint32_t* b) {
    asm volatile(
        "mma.sync.aligned.m16n8k16.row.col.f32.f16.f16.f32 "
        "{%0,%1,%2,%3},{%4,%5,%6,%7},{%8,%9},{%0,%1,%2,%3};"
        : "+f"(d[0]), "+f"(d[1]), "+f"(d[2]), "+f"(d[3])
        : "r"(a[0]), "r"(a[1]), "r"(a[2]), "r"(a[3]), "r"(b[0]), "r"(b[1]));
}

// Stage: A 64x128B (8KB) @0, BE 128x128B (16KB) @8192, BO (16KB) @24576.
#define A_BYTES    8192
#define BT_BYTES   16384
#define STAGE_BYTES 40960
#define GEMM_SMEM  (2 * STAGE_BYTES)   // 81920; two CTAs/SM; epilogue needs 67584

__global__ void __launch_bounds__(256, 2) gemm_mma_kernel() {
    extern __shared__ char smem[];
    const int tid = threadIdx.x;
    const int wid = tid >> 5;        // 0..7
    const int lane = tid & 31;
    const int m0 = blockIdx.y * 64;
    const int j0 = blockIdx.x * 128;

    const uint32_t sbase = smem_u32(smem);

    // ---- loader mappings ----
    // A: 512 16B-chunks, 2 per thread; B(E/O): 1024 chunks each, 4 per thread.
    uint32_t aoff[2], boff[4];
    const __half* gAp[2];
    const __half* gBep[4];
    const __half* gBop[4];
#pragma unroll
    for (int q = 0; q < 2; ++q) {
        int chunk = tid + q * 256;
        int row = chunk >> 3, slot = chunk & 7;
        aoff[q] = SW128((uint32_t)row * 128 + slot * 16);
        gAp[q] = g_A + (size_t)(m0 + row) * KHALF + slot * 8;
    }
#pragma unroll
    for (int q = 0; q < 4; ++q) {
        int chunk = tid + q * 256;
        int row = chunk >> 3, slot = chunk & 7;
        boff[q] = SW128((uint32_t)row * 128 + slot * 16);
        gBep[q] = g_B + (size_t)(j0 + row) * 512 + slot * 8;
        gBop[q] = gBep[q] + 256;
    }

#define ISSUE_LOAD(it, buf) do {                                               \
    uint32_t _b = sbase + (buf) * STAGE_BYTES;                                 \
    _Pragma("unroll")                                                          \
    for (int q = 0; q < 2; ++q) CP16(_b + aoff[q], gAp[q] + (it) * 64);        \
    _Pragma("unroll")                                                          \
    for (int q = 0; q < 4; ++q) {                                              \
        CP16(_b + A_BYTES + boff[q],            gBep[q] + (it) * 64);          \
        CP16(_b + A_BYTES + BT_BYTES + boff[q], gBop[q] + (it) * 64);          \
    }                                                                          \
} while (0)

    // ---- warp grid 4(m) x 2(n); warp tile 16m x 64j ----
    const int wm = wid >> 1;         // 0..3
    const int wn = wid & 1;          // 0..1
    const int arow = wm * 16 + (lane & 15);
    const int abyt = (lane >> 4) * 16;
    const int brow = wn * 64 + ((lane >> 4) << 3) + (lane & 7);
    const int bbyt = ((lane >> 3) & 1) * 16;

    float accE[8][4], accO[8][4];
#pragma unroll
    for (int jt = 0; jt < 8; ++jt)
#pragma unroll
        for (int e = 0; e < 4; ++e) { accE[jt][e] = 0.f; accO[jt][e] = 0.f; }

    ISSUE_LOAD(0, 0); CP_COMMIT();
    ISSUE_LOAD(1, 1); CP_COMMIT();

    for (int it = 0; it < NITER; ++it) {
        if (it < NITER - 1) CP_WAIT1(); else CP_WAIT0();
        __syncthreads();

        const uint32_t bA = sbase + (it & 1) * STAGE_BYTES;
        const uint32_t bE = bA + A_BYTES;
        const uint32_t bO = bE + BT_BYTES;
#pragma unroll
        for (int s = 0; s < 4; ++s) {
            uint32_t a[4];
            ldsm4(a, bA + SW128((uint32_t)arow * 128 + s * 32 + abyt));
#pragma unroll
            for (int p = 0; p < 4; ++p) {
                uint32_t be[4], bo[4];
                ldsm4(be, bE + SW128((uint32_t)(brow + p * 16) * 128 + s * 32 + bbyt));
                ldsm4(bo, bO + SW128((uint32_t)(brow + p * 16) * 128 + s * 32 + bbyt));
                mma16816(accE[2 * p],     a, &be[0]);
                mma16816(accE[2 * p + 1], a, &be[2]);
                mma16816(accO[2 * p],     a, &bo[0]);
                mma16816(accO[2 * p + 1], a, &bo[2]);
            }
        }

        __syncthreads();   // all warps done with buffer (it&1) before reuse
        if (it + 2 < NITER) { ISSUE_LOAD(it + 2, it & 1); CP_COMMIT(); }
    }

    // ---- epilogue: stage E,O to smem (64x132 each), butterfly, fp16 stores ----
    float* smE = (float*)smem;
    float* smO = smE + 64 * 132;     // total 67584 B <= 81920
    {
        const int r0 = wm * 16 + (lane >> 2);
        const int c0 = wn * 64 + (lane & 3) * 2;
#pragma unroll
        for (int jt = 0; jt < 8; ++jt) {
            int c = c0 + jt * 8;
            smE[r0 * 132 + c]           = accE[jt][0];
            smE[r0 * 132 + c + 1]       = accE[jt][1];
            smE[(r0 + 8) * 132 + c]     = accE[jt][2];
            smE[(r0 + 8) * 132 + c + 1] = accE[jt][3];
            smO[r0 * 132 + c]           = accO[jt][0];
            smO[r0 * 132 + c + 1]       = accO[jt][1];
            smO[(r0 + 8) * 132 + c]     = accO[jt][2];
            smO[(r0 + 8) * 132 + c + 1] = accO[jt][3];
        }
    }
    __syncthreads();

    // warp wid -> klocs wid*4 .. wid*4+3; lane -> 4 j's
    const int jl = lane * 4;
    const size_t jg = (size_t)j0 + jl;
#pragma unroll
    for (int h = 0; h < 4; ++h) {
        int kloc = wid * 4 + h;              // 0..31
        int kg = (m0 >> 1) + kloc;
        if (kg > 512) break;                 // warp-uniform
        float4 er  = *(float4*)&smE[(2 * kloc) * 132 + jl];
        float4 ei  = *(float4*)&smE[(2 * kloc + 1) * 132 + jl];
        float4 o_r = *(float4*)&smO[(2 * kloc) * 132 + jl];
        float4 oi  = *(float4*)&smO[(2 * kloc + 1) * 132 + jl];
        float cw = g_cos_tab[kg];
        float sw = g_msin_tab[kg];

        float prx = cw * o_r.x - sw * oi.x, pix = cw * oi.x + sw * o_r.x;
        float pry = cw * o_r.y - sw * oi.y, piy = cw * oi.y + sw * o_r.y;
        float prz = cw * o_r.z - sw * oi.z, piz = cw * oi.z + sw * o_r.z;
        float prw = cw * o_r.w - sw * oi.w, piw = cw * oi.w + sw * o_r.w;

        __half2 ur_lo = __floats2half2_rn(er.x + prx, er.y + pry);
        __half2 ur_hi = __floats2half2_rn(er.z + prz, er.w + prw);
        __half2 ui_lo = __floats2half2_rn(ei.x + pix, ei.y + piy);
        __half2 ui_hi = __floats2half2_rn(ei.z + piz, ei.w + piw);
        __half2 vr_lo = __floats2half2_rn(er.x - prx, er.y - pry);
        __half2 vr_hi = __floats2half2_rn(er.z - prz, er.w - prw);
        __half2 vi_lo = __floats2half2_rn(pix - ei.x, piy - ei.y);
        __half2 vi_hi = __floats2half2_rn(piz - ei.z, piw - ei.w);

        int k2 = 1024 - kg;
        *(__half2*)(g_Uh + (size_t)kg * NJ + jg)            = ur_lo;
        *(__half2*)(g_Uh + (size_t)kg * NJ + jg + 2)        = ur_hi;
        *(__half2*)(g_Uh + (size_t)(KF + kg) * NJ + jg)     = ui_lo;
        *(__half2*)(g_Uh + (size_t)(KF + kg) * NJ + jg + 2) = ui_hi;
        *(__half2*)(g_Uh + (size_t)k2 * NJ + jg)            = vr_lo;
        *(__half2*)(g_Uh + (size_t)k2 * NJ + jg + 2)        = vr_hi;
        *(__half2*)(g_Uh + (size_t)(KF + k2) * NJ + jg)     = vi_lo;
        *(__half2*)(g_Uh + (size_t)(KF + k2) * NJ + jg + 2) = vi_hi;
    }
}

// ============================ combine (half U, t-vectorized) ============================
__device__ __forceinline__ void load8h(const __half* p, float* dst) {
    uint2 v0 = *(const uint2*)p;
    uint2 v1 = *(const uint2*)(p + 4);
    __half2* h = (__half2*)&v0;
    float2 f;
    f = __half22float2(h[0]); dst[0] = f.x; dst[1] = f.y;
    f = __half22float2(h[1]); dst[2] = f.x; dst[3] = f.y;
    h = (__half2*)&v1;
    f = __half22float2(h[0]); dst[4] = f.x; dst[5] = f.y;
    f = __half22float2(h[1]); dst[6] = f.x; dst[7] = f.y;
}

__global__ void __launch_bounds__(128) combine5_kernel(float* __restrict__ out) {
    __shared__ float sfr[4][2][128];
    __shared__ float sfi[4][2][128];
    const int bc   = blockIdx.z;
    const int lane = threadIdx.x;
    const int ty   = threadIdx.y;
    const int tbase = blockIdx.x * 128;
    const int kb   = (blockIdx.y * 4 + ty) * 32;
    if (kb > 1024) return;

    const int t4  = tbase + lane * 4;
    const int tt4 = (t4 <= 512) ? t4 : 512;
    const size_t jj = (size_t)bc * NSEG + tt4;
    const long baseT = (long)bc * KF;

    float pXr0[4], pXr1[4], pXi0[4], pXi1[4];
#pragma unroll
    for (int e = 0; e < 4; ++e) { pXr0[e] = pXr1[e] = pXi0[e] = pXi1[e] = 0.f; }

#pragma unroll 2
    for (int i = 0; i < 34; ++i) {
        int k = kb - 1 + i;
        int kk = k;
        float sgn = 1.f;
        if (kk < 0)         { kk = -kk;       sgn = -1.f; }
        else if (kk > 1024) { kk = 2048 - kk; sgn = -1.f; }

        float rr[8], ii[8];
        load8h(g_Uh + (size_t)kk * NJ + jj, rr);
        load8h(g_Uh + (size_t)(KF + kk) * NJ + jj, ii);

        float xr[4], xi[4];
        switch (kk & 3) {
            case 0:
#pragma unroll
                for (int e = 0; e < 4; ++e) {
                    xr[e] = rr[e] + rr[e+1] + rr[e+2] + rr[e+3];
                    xi[e] = sgn * (ii[e] + ii[e+1] + ii[e+2] + ii[e+3]);
                }
                break;
            case 1:
#pragma unroll
                for (int e = 0; e < 4; ++e) {
                    xr[e] = rr[e] + ii[e+1] - rr[e+2] - ii[e+3];
                    xi[e] = sgn * (ii[e] - rr[e+1] - ii[e+2] + rr[e+3]);
                }
                break;
            case 2:
#pragma unroll
                for (int e = 0; e < 4; ++e) {
                    xr[e] = rr[e] - rr[e+1] + rr[e+2] - rr[e+3];
                    xi[e] = sgn * (ii[e] - ii[e+1] + ii[e+2] - ii[e+3]);
                }
                break;
            default:
#pragma unroll
                for (int e = 0; e < 4; ++e) {
                    xr[e] = rr[e] - ii[e+1] - rr[e+2] + ii[e+3];
                    xi[e] = sgn * (ii[e] + rr[e+1] - ii[e+2] - rr[e+3]);
                }
                break;
        }

        if (i >= 2) {
            const int ko = k - 1;
            const int buf = i & 1;
            float4 vr, vi;
            vr.x = 0.5f * pXr1[0] - 0.25f * (pXr0[0] + xr[0]);
            vr.y = 0.5f * pXr1[1] - 0.25f * (pXr0[1] + xr[1]);
            vr.z = 0.5f * pXr1[2] - 0.25f * (pXr0[2] + xr[2]);
            vr.w = 0.5f * pXr1[3] - 0.25f * (pXr0[3] + xr[3]);
            vi.x = 0.5f * pXi1[0] - 0.25f * (pXi0[0] + xi[0]);
            vi.y = 0.5f * pXi1[1] - 0.25f * (pXi0[1] + xi[1]);
            vi.z = 0.5f * pXi1[2] - 0.25f * (pXi0[2] + xi[2]);
            vi.w = 0.5f * pXi1[3] - 0.25f * (pXi0[3] + xi[3]);
            *(float4*)&sfr[ty][buf][lane * 4] = vr;
            *(float4*)&sfi[ty][buf][lane * 4] = vi;
            __syncwarp();
            if (ko <= 1024) {
                const long baseR = (baseT + ko) * NT;
#pragma unroll
                for (int e = 0; e < 4; ++e) {
                    int t = tbase + 32 * e + lane;
                    if (t <= 512) {
                        out[baseR + t]            = sfr[ty][buf][32 * e + lane];
                        out[IMAG_OFF + baseR + t] = sfi[ty][buf][32 * e + lane];
                    }
                }
            }
        }
#pragma unroll
        for (int e = 0; e < 4; ++e) {
            pXr0[e] = pXr1[e]; pXr1[e] = xr[e];
            pXi0[e] = pXi1[e]; pXi1[e] = xi[e];
        }
    }
}

// ============================ launch ============================
extern "C" void kernel_launch(void* const* d_in, const int* in_sizes, int n_in,
                              void* d_out, int out_size)
{
    const float* x = (const float*)d_in[0];
    float* out = (float*)d_out;

    cudaFuncSetAttribute(gemm_mma_kernel,
                         cudaFuncAttributeMaxDynamicSharedMemorySize, GEMM_SMEM);

    init_tab_kernel<<<8, 256>>>();
    pack_a_kernel<<<(MROWSA * KHALF) / 512, 256>>>();
    pack_b_kernel<<<NJ, 256>>>(x);
    gemm_mma_kernel<<<dim3(NJ / 128, 17), 256, GEMM_SMEM>>>();
    combine5_kernel<<<dim3(5, 9, NBC), dim3(32, 4)>>>(out);
}

// round 12
// speedup vs baseline: 1.3640x; 1.0506x over previous
#include <cuda_runtime.h>
#include <cuda_fp16.h>
#include <cstdint>

// STFT via hop-polyphase + one radix-2 DIT level + freq-domain hann.
//   E_k, O_k = 256-pt DFTs (1024-periodic) of even/odd samples, same weights.
//   U_k = E_k + w^k O_k, k=0..512; U_{1024-k} = conj(E_k - w^k O_k).
//   GEMM: CTA tile 64m x 128j, K=256, dual acc (E,O), warp tile 32m x 32j.
//   U stored fp16. Combine: X_t[k] = sum_q (-i)^{kq} U_{t+q}[k];
//   F = 0.5X[k] - 0.25(X[k-1]+X[k+1]).

#define KF     1025
#define NBC    32
#define LEN    262144
#define NT     513
#define NSEG   516
#define NJ     (NBC * NSEG)      // 16512
#define MROWSA 1152
#define KHALF  256
#define NITER  4                 // KHALF / 64
#define IMAG_OFF 16826400L

__device__ __half g_A[(size_t)MROWSA * KHALF];
__device__ __half g_B[(size_t)NJ * 512];        // [j][c]: c<256 even, else odd
__device__ __half g_Uh[(size_t)2050 * NJ + 32]; // rows 0..1024 re, 1025..2049 im
__device__ float  g_cos_tab[2048];
__device__ float  g_msin_tab[2048];

#define SW128(b) ((b) ^ (((b) >> 3) & 0x70))

// ============================ DFT tables ============================
__global__ void init_tab_kernel() {
    int i = blockIdx.x * 256 + threadIdx.x;
    float a = (float)i * (1.0f / 1024.0f);
    g_cos_tab[i]  = cospif(a);
    g_msin_tab[i] = -sinpif(a);
}

// ============================ pack A ============================
__global__ void pack_a_kernel() {
    int idx2 = (blockIdx.x * 256 + threadIdx.x) * 2;
    int m = idx2 >> 8;
    int c = idx2 & 255;
    __half o[2];
    if (m < 1026) {
        int k = m >> 1;
        const float* tab = (m & 1) ? g_msin_tab : g_cos_tab;
        o[0] = __float2half_rn(tab[(2 * k * c) & 2047]);
        o[1] = __float2half_rn(tab[(2 * k * (c + 1)) & 2047]);
    } else {
        o[0] = o[1] = __float2half_rn(0.f);
    }
    *(__half2*)&g_A[(size_t)m * KHALF + c] = *(__half2*)o;
}

// ============================ pack B (even/odd split) ============================
__global__ void pack_b_kernel(const float* __restrict__ x) {
    int j  = blockIdx.x;
    int bc = j / NSEG;
    int s  = j - bc * NSEG;
    __half* bj = g_B + (size_t)j * 512;
    const float* xbc = x + (size_t)bc * LEN;
    int c = threadIdx.x;            // 0..255
    int pe = s * 512 + 2 * c - 1024;
    int po = pe + 1;
    if (pe < 0) pe = -pe;
    if (pe >= LEN) pe = 2 * LEN - 2 - pe;
    if (po < 0) po = -po;
    if (po >= LEN) po = 2 * LEN - 2 - po;
    bj[c]       = __float2half_rn(xbc[pe]);
    bj[256 + c] = __float2half_rn(xbc[po]);
}

// ============================ GEMM (mma.sync fp16, dual-acc E/O) ============================
#define CP16(dst, src) \
    asm volatile("cp.async.cg.shared.global [%0], [%1], 16;" :: "r"(dst), "l"(src))
#define CP_COMMIT() asm volatile("cp.async.commit_group;" ::: "memory")
#define CP_WAIT1()  asm volatile("cp.async.wait_group 1;" ::: "memory")
#define CP_WAIT0()  asm volatile("cp.async.wait_group 0;" ::: "memory")

__device__ __forceinline__ uint32_t smem_u32(const void* p) {
    uint32_t a;
    asm("{ .reg .u64 t; cvta.to.shared.u64 t, %1; cvt.u32.u64 %0, t; }"
        : "=r"(a) : "l"(p));
    return a;
}
__device__ __forceinline__ void ldsm4(uint32_t* r, uint32_t addr) {
    asm volatile("ldmatrix.sync.aligned.m8n8.x4.shared.b16 {%0,%1,%2,%3}, [%4];"
                 : "=r"(r[0]), "=r"(r[1]), "=r"(r[2]), "=r"(r[3]) : "r"(addr));
}
__device__ __forceinline__ void mma16816(float* d, const uint32_t* a, const uint32_t* b) {
    asm volatile(
        "mma.sync.aligned.m16n8k16.row.col.f32.f16.f16.f32 "
        "{%0,%1,%2,%3},{%4,%5,%6,%7},{%8,%9},{%0,%1,%2,%3};"
        : "+f"(d[0]), "+f"(d[1]), "+f"(d[2]), "+f"(d[3])
        : "r"(a[0]), "r"(a[1]), "r"(a[2]), "r"(a[3]), "r"(b[0]), "r"(b[1]));
}

// Stage: A 64x128B (8KB) @0, BE 128x128B (16KB) @8192, BO (16KB) @24576.
#define A_BYTES    8192
#define BT_BYTES   16384
#define STAGE_BYTES 40960
#define GEMM_SMEM  (2 * STAGE_BYTES)   // 81920; two CTAs/SM; epilogue needs 67584

__global__ void __launch_bounds__(256, 2) gemm_mma_kernel() {
    extern __shared__ char smem[];
    const int tid = threadIdx.x;
    const int wid = tid >> 5;        // 0..7
    const int lane = tid & 31;
    const int m0 = blockIdx.y * 64;
    const int j0 = blockIdx.x * 128;

    const uint32_t sbase = smem_u32(smem);

    // ---- loader mappings ----
    uint32_t aoff[2], boff[4];
    const __half* gAp[2];
    const __half* gBep[4];
    const __half* gBop[4];
#pragma unroll
    for (int q = 0; q < 2; ++q) {
        int chunk = tid + q * 256;
        int row = chunk >> 3, slot = chunk & 7;
        aoff[q] = SW128((uint32_t)row * 128 + slot * 16);
        gAp[q] = g_A + (size_t)(m0 + row) * KHALF + slot * 8;
    }
#pragma unroll
    for (int q = 0; q < 4; ++q) {
        int chunk = tid + q * 256;
        int row = chunk >> 3, slot = chunk & 7;
        boff[q] = SW128((uint32_t)row * 128 + slot * 16);
        gBep[q] = g_B + (size_t)(j0 + row) * 512 + slot * 8;
        gBop[q] = gBep[q] + 256;
    }

#define ISSUE_LOAD(it, buf) do {                                               \
    uint32_t _b = sbase + (buf) * STAGE_BYTES;                                 \
    _Pragma("unroll")                                                          \
    for (int q = 0; q < 2; ++q) CP16(_b + aoff[q], gAp[q] + (it) * 64);        \
    _Pragma("unroll")                                                          \
    for (int q = 0; q < 4; ++q) {                                              \
        CP16(_b + A_BYTES + boff[q],            gBep[q] + (it) * 64);          \
        CP16(_b + A_BYTES + BT_BYTES + boff[q], gBop[q] + (it) * 64);          \
    }                                                                          \
} while (0)

    // ---- warp grid 2(m) x 4(n); warp tile 32m x 32j ----
    const int wm = wid >> 2;         // 0..1
    const int wn = wid & 3;          // 0..3
    const int arow = wm * 32 + (lane & 15);
    const int abyt = (lane >> 4) * 16;
    const int brow = wn * 32 + ((lane >> 4) << 3) + (lane & 7);
    const int bbyt = ((lane >> 3) & 1) * 16;

    float accE[2][4][4], accO[2][4][4];
#pragma unroll
    for (int i = 0; i < 2; ++i)
#pragma unroll
        for (int jt = 0; jt < 4; ++jt)
#pragma unroll
            for (int e = 0; e < 4; ++e) { accE[i][jt][e] = 0.f; accO[i][jt][e] = 0.f; }

    ISSUE_LOAD(0, 0); CP_COMMIT();
    ISSUE_LOAD(1, 1); CP_COMMIT();

    for (int it = 0; it < NITER; ++it) {
        if (it < NITER - 1) CP_WAIT1(); else CP_WAIT0();
        __syncthreads();

        const uint32_t bA = sbase + (it & 1) * STAGE_BYTES;
        const uint32_t bE = bA + A_BYTES;
        const uint32_t bO = bE + BT_BYTES;
#pragma unroll
        for (int s = 0; s < 4; ++s) {
            uint32_t a[2][4], be[2][4], bo[2][4];
#pragma unroll
            for (int i = 0; i < 2; ++i)
                ldsm4(a[i], bA + SW128((uint32_t)(arow + i * 16) * 128 + s * 32 + abyt));
#pragma unroll
            for (int p = 0; p < 2; ++p) {
                ldsm4(be[p], bE + SW128((uint32_t)(brow + p * 16) * 128 + s * 32 + bbyt));
                ldsm4(bo[p], bO + SW128((uint32_t)(brow + p * 16) * 128 + s * 32 + bbyt));
            }
#pragma unroll
            for (int i = 0; i < 2; ++i) {
#pragma unroll
                for (int p = 0; p < 2; ++p) {
                    mma16816(accE[i][2 * p],     a[i], &be[p][0]);
                    mma16816(accE[i][2 * p + 1], a[i], &be[p][2]);
                    mma16816(accO[i][2 * p],     a[i], &bo[p][0]);
                    mma16816(accO[i][2 * p + 1], a[i], &bo[p][2]);
                }
            }
        }

        __syncthreads();   // all warps done with buffer (it&1) before reuse
        if (it + 2 < NITER) { ISSUE_LOAD(it + 2, it & 1); CP_COMMIT(); }
    }

    // ---- epilogue: stage E,O to smem (64x132 each), butterfly, fp16 stores ----
    float* smE = (float*)smem;
    float* smO = smE + 64 * 132;     // total 67584 B <= 81920
    {
        const int r0 = wm * 32 + (lane >> 2);
        const int c0 = wn * 32 + (lane & 3) * 2;
#pragma unroll
        for (int i = 0; i < 2; ++i) {
            int r = r0 + i * 16;
#pragma unroll
            for (int jt = 0; jt < 4; ++jt) {
                int c = c0 + jt * 8;
                smE[r * 132 + c]           = accE[i][jt][0];
                smE[r * 132 + c + 1]       = accE[i][jt][1];
                smE[(r + 8) * 132 + c]     = accE[i][jt][2];
                smE[(r + 8) * 132 + c + 1] = accE[i][jt][3];
                smO[r * 132 + c]           = accO[i][jt][0];
                smO[r * 132 + c + 1]       = accO[i][jt][1];
                smO[(r + 8) * 132 + c]     = accO[i][jt][2];
                smO[(r + 8) * 132 + c + 1] = accO[i][jt][3];
            }
        }
    }
    __syncthreads();

    // warp wid -> klocs wid*4 .. wid*4+3; lane -> 4 j's
    const int jl = lane * 4;
    const size_t jg = (size_t)j0 + jl;
#pragma unroll
    for (int h = 0; h < 4; ++h) {
        int kloc = wid * 4 + h;              // 0..31
        int kg = (m0 >> 1) + kloc;
        if (kg > 512) break;                 // warp-uniform
        float4 er  = *(float4*)&smE[(2 * kloc) * 132 + jl];
        float4 ei  = *(float4*)&smE[(2 * kloc + 1) * 132 + jl];
        float4 o_r = *(float4*)&smO[(2 * kloc) * 132 + jl];
        float4 oi  = *(float4*)&smO[(2 * kloc + 1) * 132 + jl];
        float cw = g_cos_tab[kg];
        float sw = g_msin_tab[kg];

        float prx = cw * o_r.x - sw * oi.x, pix = cw * oi.x + sw * o_r.x;
        float pry = cw * o_r.y - sw * oi.y, piy = cw * oi.y + sw * o_r.y;
        float prz = cw * o_r.z - sw * oi.z, piz = cw * oi.z + sw * o_r.z;
        float prw = cw * o_r.w - sw * oi.w, piw = cw * oi.w + sw * o_r.w;

        __half2 ur_lo = __floats2half2_rn(er.x + prx, er.y + pry);
        __half2 ur_hi = __floats2half2_rn(er.z + prz, er.w + prw);
        __half2 ui_lo = __floats2half2_rn(ei.x + pix, ei.y + piy);
        __half2 ui_hi = __floats2half2_rn(ei.z + piz, ei.w + piw);
        __half2 vr_lo = __floats2half2_rn(er.x - prx, er.y - pry);
        __half2 vr_hi = __floats2half2_rn(er.z - prz, er.w - prw);
        __half2 vi_lo = __floats2half2_rn(pix - ei.x, piy - ei.y);
        __half2 vi_hi = __floats2half2_rn(piz - ei.z, piw - ei.w);

        int k2 = 1024 - kg;
        *(__half2*)(g_Uh + (size_t)kg * NJ + jg)            = ur_lo;
        *(__half2*)(g_Uh + (size_t)kg * NJ + jg + 2)        = ur_hi;
        *(__half2*)(g_Uh + (size_t)(KF + kg) * NJ + jg)     = ui_lo;
        *(__half2*)(g_Uh + (size_t)(KF + kg) * NJ + jg + 2) = ui_hi;
        *(__half2*)(g_Uh + (size_t)k2 * NJ + jg)            = vr_lo;
        *(__half2*)(g_Uh + (size_t)k2 * NJ + jg + 2)        = vr_hi;
        *(__half2*)(g_Uh + (size_t)(KF + k2) * NJ + jg)     = vi_lo;
        *(__half2*)(g_Uh + (size_t)(KF + k2) * NJ + jg + 2) = vi_hi;
    }
}

// ============================ combine (half U, t-vectorized) ============================
__device__ __forceinline__ void load8h(const __half* p, float* dst) {
    uint2 v0 = *(const uint2*)p;
    uint2 v1 = *(const uint2*)(p + 4);
    __half2* h = (__half2*)&v0;
    float2 f;
    f = __half22float2(h[0]); dst[0] = f.x; dst[1] = f.y;
    f = __half22float2(h[1]); dst[2] = f.x; dst[3] = f.y;
    h = (__half2*)&v1;
    f = __half22float2(h[0]); dst[4] = f.x; dst[5] = f.y;
    f = __half22float2(h[1]); dst[6] = f.x; dst[7] = f.y;
}

__global__ void __launch_bounds__(128) combine5_kernel(float* __restrict__ out) {
    __shared__ float sfr[4][2][128];
    __shared__ float sfi[4][2][128];
    const int bc   = blockIdx.z;
    const int lane = threadIdx.x;
    const int ty   = threadIdx.y;
    const int tbase = blockIdx.x * 128;
    const int kb   = (blockIdx.y * 4 + ty) * 32;
    if (kb > 1024) return;

    const int t4  = tbase + lane * 4;
    const int tt4 = (t4 <= 512) ? t4 : 512;
    const size_t jj = (size_t)bc * NSEG + tt4;
    const long baseT = (long)bc * KF;

    float pXr0[4], pXr1[4], pXi0[4], pXi1[4];
#pragma unroll
    for (int e = 0; e < 4; ++e) { pXr0[e] = pXr1[e] = pXi0[e] = pXi1[e] = 0.f; }

#pragma unroll 2
    for (int i = 0; i < 34; ++i) {
        int k = kb - 1 + i;
        int kk = k;
        float sgn = 1.f;
        if (kk < 0)         { kk = -kk;       sgn = -1.f; }
        else if (kk > 1024) { kk = 2048 - kk; sgn = -1.f; }

        float rr[8], ii[8];
        load8h(g_Uh + (size_t)kk * NJ + jj, rr);
        load8h(g_Uh + (size_t)(KF + kk) * NJ + jj, ii);

        float xr[4], xi[4];
        switch (kk & 3) {
            case 0:
#pragma unroll
                for (int e = 0; e < 4; ++e) {
                    xr[e] = rr[e] + rr[e+1] + rr[e+2] + rr[e+3];
                    xi[e] = sgn * (ii[e] + ii[e+1] + ii[e+2] + ii[e+3]);
                }
                break;
            case 1:
#pragma unroll
                for (int e = 0; e < 4; ++e) {
                    xr[e] = rr[e] + ii[e+1] - rr[e+2] - ii[e+3];
                    xi[e] = sgn * (ii[e] - rr[e+1] - ii[e+2] + rr[e+3]);
                }
                break;
            case 2:
#pragma unroll
                for (int e = 0; e < 4; ++e) {
                    xr[e] = rr[e] - rr[e+1] + rr[e+2] - rr[e+3];
                    xi[e] = sgn * (ii[e] - ii[e+1] + ii[e+2] - ii[e+3]);
                }
                break;
            default:
#pragma unroll
                for (int e = 0; e < 4; ++e) {
                    xr[e] = rr[e] - ii[e+1] - rr[e+2] + ii[e+3];
                    xi[e] = sgn * (ii[e] + rr[e+1] - ii[e+2] - rr[e+3]);
                }
                break;
        }

        if (i >= 2) {
            const int ko = k - 1;
            const int buf = i & 1;
            float4 vr, vi;
            vr.x = 0.5f * pXr1[0] - 0.25f * (pXr0[0] + xr[0]);
            vr.y = 0.5f * pXr1[1] - 0.25f * (pXr0[1] + xr[1]);
            vr.z = 0.5f * pXr1[2] - 0.25f * (pXr0[2] + xr[2]);
            vr.w = 0.5f * pXr1[3] - 0.25f * (pXr0[3] + xr[3]);
            vi.x = 0.5f * pXi1[0] - 0.25f * (pXi0[0] + xi[0]);
            vi.y = 0.5f * pXi1[1] - 0.25f * (pXi0[1] + xi[1]);
            vi.z = 0.5f * pXi1[2] - 0.25f * (pXi0[2] + xi[2]);
            vi.w = 0.5f * pXi1[3] - 0.25f * (pXi0[3] + xi[3]);
            *(float4*)&sfr[ty][buf][lane * 4] = vr;
            *(float4*)&sfi[ty][buf][lane * 4] = vi;
            __syncwarp();
            if (ko <= 1024) {
                const long baseR = (baseT + ko) * NT;
#pragma unroll
                for (int e = 0; e < 4; ++e) {
                    int t = tbase + 32 * e + lane;
                    if (t <= 512) {
                        out[baseR + t]            = sfr[ty][buf][32 * e + lane];
                        out[IMAG_OFF + baseR + t] = sfi[ty][buf][32 * e + lane];
                    }
                }
            }
        }
#pragma unroll
        for (int e = 0; e < 4; ++e) {
            pXr0[e] = pXr1[e]; pXr1[e] = xr[e];
            pXi0[e] = pXi1[e]; pXi1[e] = xi[e];
        }
    }
}

// ============================ launch ============================
extern "C" void kernel_launch(void* const* d_in, const int* in_sizes, int n_in,
                              void* d_out, int out_size)
{
    const float* x = (const float*)d_in[0];
    float* out = (float*)d_out;

    cudaFuncSetAttribute(gemm_mma_kernel,
                         cudaFuncAttributeMaxDynamicSharedMemorySize, GEMM_SMEM);

    init_tab_kernel<<<8, 256>>>();
    pack_a_kernel<<<(MROWSA * KHALF) / 512, 256>>>();
    pack_b_kernel<<<NJ, 256>>>(x);
    gemm_mma_kernel<<<dim3(NJ / 128, 17), 256, GEMM_SMEM>>>();
    combine5_kernel<<<dim3(5, 9, NBC), dim3(32, 4)>>>(out);
}

// round 13
// speedup vs baseline: 1.3911x; 1.0199x over previous
#include <cuda_runtime.h>
#include <cuda_fp16.h>
#include <cstdint>

// STFT via hop-polyphase + one radix-2 DIT level + freq-domain hann.
//   E_k, O_k = 256-pt DFTs (1024-periodic) of even/odd samples, same weights.
//   U_k = E_k + w^k O_k, k=0..512; U_{1024-k} = conj(E_k - w^k O_k).
//   GEMM: CTA 64m x 128j, K=256, dual acc (E,O), warp tile 32x32, U fp16.
//   Combine: X_t[k] = sum_q (-i)^{kq} U_{t+q}[k]; F = 0.5X - 0.25(X[k-1]+X[k+1]).

#define KF     1025
#define NBC    32
#define LEN    262144
#define NT     513
#define NSEG   516
#define NJ     (NBC * NSEG)      // 16512
#define MROWSA 1152
#define KHALF  256
#define NITER  4                 // KHALF / 64
#define IMAG_OFF 16826400L

__device__ __half g_A[(size_t)MROWSA * KHALF];
__device__ __half g_B[(size_t)NJ * 512];        // [j][c]: c<256 even, else odd
__device__ __half g_Uh[(size_t)2050 * NJ + 32]; // rows 0..1024 re, 1025..2049 im
__device__ float  g_cos_tab[2048];
__device__ float  g_msin_tab[2048];

#define SW128(b) ((b) ^ (((b) >> 3) & 0x70))

// ============================ fused prep: pack_b + pack_a + tables ============================
// blocks [0, NJ/2): pack_b, 2 j's per block (128 threads each, float4 loads)
// blocks [NJ/2, NJ/2+576): pack_a (direct cospif/sinpif)
// blocks [NJ/2+576, NJ/2+584): DFT tables for GEMM epilogue
#define PREP_PB (NJ / 2)          // 8256
#define PREP_PA 576
#define PREP_GRID (PREP_PB + PREP_PA + 8)

__global__ void prep_kernel(const float* __restrict__ x) {
    const int b = blockIdx.x;
    const int tid = threadIdx.x;
    if (b < PREP_PB) {
        // ---- pack B ----
        int j  = 2 * b + (tid >> 7);
        int bc = j / NSEG;
        int s  = j - bc * NSEG;
        const float* xbc = x + (size_t)bc * LEN;
        __half* bj = g_B + (size_t)j * 512;
        int c4 = tid & 127;                      // handles samples 4c4..4c4+3
        int p0 = s * 512 - 1024 + 4 * c4;
        float4 v;
        if (s >= 2 && s <= 513) {                // fully in-range (block-uniform)
            v = *(const float4*)(xbc + p0);
        } else {
            float tmp[4];
#pragma unroll
            for (int e = 0; e < 4; ++e) {
                int p = p0 + e;
                if (p < 0) p = -p;
                if (p >= LEN) p = 2 * LEN - 2 - p;
                tmp[e] = xbc[p];
            }
            v = make_float4(tmp[0], tmp[1], tmp[2], tmp[3]);
        }
        *(__half2*)&bj[2 * c4]       = __floats2half2_rn(v.x, v.z);  // even
        *(__half2*)&bj[256 + 2 * c4] = __floats2half2_rn(v.y, v.w);  // odd
    } else if (b < PREP_PB + PREP_PA) {
        // ---- pack A ----
        int idx2 = ((b - PREP_PB) * 256 + tid) * 2;
        int m = idx2 >> 8;
        int c = idx2 & 255;
        __half o[2];
        if (m < 1026) {
            int k = m >> 1;
            if (m & 1) {
                o[0] = __float2half_rn(-sinpif((float)((2 * k * c) & 2047) * (1.0f / 1024.0f)));
                o[1] = __float2half_rn(-sinpif((float)((2 * k * (c + 1)) & 2047) * (1.0f / 1024.0f)));
            } else {
                o[0] = __float2half_rn(cospif((float)((2 * k * c) & 2047) * (1.0f / 1024.0f)));
                o[1] = __float2half_rn(cospif((float)((2 * k * (c + 1)) & 2047) * (1.0f / 1024.0f)));
            }
        } else {
            o[0] = o[1] = __float2half_rn(0.f);
        }
        *(__half2*)&g_A[(size_t)m * KHALF + c] = *(__half2*)o;
    } else {
        // ---- tables (for GEMM epilogue twiddles) ----
        int i = (b - PREP_PB - PREP_PA) * 256 + tid;
        float a = (float)i * (1.0f / 1024.0f);
        g_cos_tab[i]  = cospif(a);
        g_msin_tab[i] = -sinpif(a);
    }
}

// ============================ GEMM (mma.sync fp16, dual-acc E/O) ============================
#define CP16(dst, src) \
    asm volatile("cp.async.cg.shared.global [%0], [%1], 16;" :: "r"(dst), "l"(src))
#define CP_COMMIT() asm volatile("cp.async.commit_group;" ::: "memory")
#define CP_WAIT1()  asm volatile("cp.async.wait_group 1;" ::: "memory")
#define CP_WAIT0()  asm volatile("cp.async.wait_group 0;" ::: "memory")

__device__ __forceinline__ uint32_t smem_u32(const void* p) {
    uint32_t a;
    asm("{ .reg .u64 t; cvta.to.shared.u64 t, %1; cvt.u32.u64 %0, t; }"
        : "=r"(a) : "l"(p));
    return a;
}
__device__ __forceinline__ void ldsm4(uint32_t* r, uint32_t addr) {
    asm volatile("ldmatrix.sync.aligned.m8n8.x4.shared.b16 {%0,%1,%2,%3}, [%4];"
                 : "=r"(r[0]), "=r"(r[1]), "=r"(r[2]), "=r"(r[3]) : "r"(addr));
}
__device__ __forceinline__ void mma16816(float* d, const uint32_t* a, const uint32_t* b) {
    asm volatile(
        "mma.sync.aligned.m16n8k16.row.col.f32.f16.f16.f32 "
        "{%0,%1,%2,%3},{%4,%5,%6,%7},{%8,%9},{%0,%1,%2,%3};"
        : "+f"(d[0]), "+f"(d[1]), "+f"(d[2]), "+f"(d[3])
        : "r"(a[0]), "r"(a[1]), "r"(a[2]), "r"(a[3]), "r"(b[0]), "r"(b[1]));
}

#define A_BYTES    8192
#define BT_BYTES   16384
#define STAGE_BYTES 40960
#define GEMM_SMEM  (2 * STAGE_BYTES)   // 81920; two CTAs/SM; epilogue needs 67584

__global__ void __launch_bounds__(256, 2) gemm_mma_kernel() {
    extern __shared__ char smem[];
    const int tid = threadIdx.x;
    const int wid = tid >> 5;
    const int lane = tid & 31;
    const int m0 = blockIdx.y * 64;
    const int j0 = blockIdx.x * 128;

    const uint32_t sbase = smem_u32(smem);

    uint32_t aoff[2], boff[4];
    const __half* gAp[2];
    const __half* gBep[4];
    const __half* gBop[4];
#pragma unroll
    for (int q = 0; q < 2; ++q) {
        int chunk = tid + q * 256;
        int row = chunk >> 3, slot = chunk & 7;
        aoff[q] = SW128((uint32_t)row * 128 + slot * 16);
        gAp[q] = g_A + (size_t)(m0 + row) * KHALF + slot * 8;
    }
#pragma unroll
    for (int q = 0; q < 4; ++q) {
        int chunk = tid + q * 256;
        int row = chunk >> 3, slot = chunk & 7;
        boff[q] = SW128((uint32_t)row * 128 + slot * 16);
        gBep[q] = g_B + (size_t)(j0 + row) * 512 + slot * 8;
        gBop[q] = gBep[q] + 256;
    }

#define ISSUE_LOAD(it, buf) do {                                               \
    uint32_t _b = sbase + (buf) * STAGE_BYTES;                                 \
    _Pragma("unroll")                                                          \
    for (int q = 0; q < 2; ++q) CP16(_b + aoff[q], gAp[q] + (it) * 64);        \
    _Pragma("unroll")                                                          \
    for (int q = 0; q < 4; ++q) {                                              \
        CP16(_b + A_BYTES + boff[q],            gBep[q] + (it) * 64);          \
        CP16(_b + A_BYTES + BT_BYTES + boff[q], gBop[q] + (it) * 64);          \
    }                                                                          \
} while (0)

    const int wm = wid >> 2;
    const int wn = wid & 3;
    const int arow = wm * 32 + (lane & 15);
    const int abyt = (lane >> 4) * 16;
    const int brow = wn * 32 + ((lane >> 4) << 3) + (lane & 7);
    const int bbyt = ((lane >> 3) & 1) * 16;

    float accE[2][4][4], accO[2][4][4];
#pragma unroll
    for (int i = 0; i < 2; ++i)
#pragma unroll
        for (int jt = 0; jt < 4; ++jt)
#pragma unroll
            for (int e = 0; e < 4; ++e) { accE[i][jt][e] = 0.f; accO[i][jt][e] = 0.f; }

    ISSUE_LOAD(0, 0); CP_COMMIT();
    ISSUE_LOAD(1, 1); CP_COMMIT();

    for (int it = 0; it < NITER; ++it) {
        if (it < NITER - 1) CP_WAIT1(); else CP_WAIT0();
        __syncthreads();

        const uint32_t bA = sbase + (it & 1) * STAGE_BYTES;
        const uint32_t bE = bA + A_BYTES;
        const uint32_t bO = bE + BT_BYTES;
#pragma unroll
        for (int s = 0; s < 4; ++s) {
            uint32_t a[2][4], be[2][4], bo[2][4];
#pragma unroll
            for (int i = 0; i < 2; ++i)
                ldsm4(a[i], bA + SW128((uint32_t)(arow + i * 16) * 128 + s * 32 + abyt));
#pragma unroll
            for (int p = 0; p < 2; ++p) {
                ldsm4(be[p], bE + SW128((uint32_t)(brow + p * 16) * 128 + s * 32 + bbyt));
                ldsm4(bo[p], bO + SW128((uint32_t)(brow + p * 16) * 128 + s * 32 + bbyt));
            }
#pragma unroll
            for (int i = 0; i < 2; ++i) {
#pragma unroll
                for (int p = 0; p < 2; ++p) {
                    mma16816(accE[i][2 * p],     a[i], &be[p][0]);
                    mma16816(accE[i][2 * p + 1], a[i], &be[p][2]);
                    mma16816(accO[i][2 * p],     a[i], &bo[p][0]);
                    mma16816(accO[i][2 * p + 1], a[i], &bo[p][2]);
                }
            }
        }

        __syncthreads();
        if (it + 2 < NITER) { ISSUE_LOAD(it + 2, it & 1); CP_COMMIT(); }
    }

    // ---- epilogue: stage E,O to smem (64x132 each), butterfly, fp16 stores ----
    float* smE = (float*)smem;
    float* smO = smE + 64 * 132;
    {
        const int r0 = wm * 32 + (lane >> 2);
        const int c0 = wn * 32 + (lane & 3) * 2;
#pragma unroll
        for (int i = 0; i < 2; ++i) {
            int r = r0 + i * 16;
#pragma unroll
            for (int jt = 0; jt < 4; ++jt) {
                int c = c0 + jt * 8;
                smE[r * 132 + c]           = accE[i][jt][0];
                smE[r * 132 + c + 1]       = accE[i][jt][1];
                smE[(r + 8) * 132 + c]     = accE[i][jt][2];
                smE[(r + 8) * 132 + c + 1] = accE[i][jt][3];
                smO[r * 132 + c]           = accO[i][jt][0];
                smO[r * 132 + c + 1]       = accO[i][jt][1];
                smO[(r + 8) * 132 + c]     = accO[i][jt][2];
                smO[(r + 8) * 132 + c + 1] = accO[i][jt][3];
            }
        }
    }
    __syncthreads();

    const int jl = lane * 4;
    const size_t jg = (size_t)j0 + jl;
#pragma unroll
    for (int h = 0; h < 4; ++h) {
        int kloc = wid * 4 + h;
        int kg = (m0 >> 1) + kloc;
        if (kg > 512) break;
        float4 er  = *(float4*)&smE[(2 * kloc) * 132 + jl];
        float4 ei  = *(float4*)&smE[(2 * kloc + 1) * 132 + jl];
        float4 o_r = *(float4*)&smO[(2 * kloc) * 132 + jl];
        float4 oi  = *(float4*)&smO[(2 * kloc + 1) * 132 + jl];
        float cw = g_cos_tab[kg];
        float sw = g_msin_tab[kg];

        float prx = cw * o_r.x - sw * oi.x, pix = cw * oi.x + sw * o_r.x;
        float pry = cw * o_r.y - sw * oi.y, piy = cw * oi.y + sw * o_r.y;
        float prz = cw * o_r.z - sw * oi.z, piz = cw * oi.z + sw * o_r.z;
        float prw = cw * o_r.w - sw * oi.w, piw = cw * oi.w + sw * o_r.w;

        __half2 ur_lo = __floats2half2_rn(er.x + prx, er.y + pry);
        __half2 ur_hi = __floats2half2_rn(er.z + prz, er.w + prw);
        __half2 ui_lo = __floats2half2_rn(ei.x + pix, ei.y + piy);
        __half2 ui_hi = __floats2half2_rn(ei.z + piz, ei.w + piw);
        __half2 vr_lo = __floats2half2_rn(er.x - prx, er.y - pry);
        __half2 vr_hi = __floats2half2_rn(er.z - prz, er.w - prw);
        __half2 vi_lo = __floats2half2_rn(pix - ei.x, piy - ei.y);
        __half2 vi_hi = __floats2half2_rn(piz - ei.z, piw - ei.w);

        int k2 = 1024 - kg;
        *(__half2*)(g_Uh + (size_t)kg * NJ + jg)            = ur_lo;
        *(__half2*)(g_Uh + (size_t)kg * NJ + jg + 2)        = ur_hi;
        *(__half2*)(g_Uh + (size_t)(KF + kg) * NJ + jg)     = ui_lo;
        *(__half2*)(g_Uh + (size_t)(KF + kg) * NJ + jg + 2) = ui_hi;
        *(__half2*)(g_Uh + (size_t)k2 * NJ + jg)            = vr_lo;
        *(__half2*)(g_Uh + (size_t)k2 * NJ + jg + 2)        = vr_hi;
        *(__half2*)(g_Uh + (size_t)(KF + k2) * NJ + jg)     = vi_lo;
        *(__half2*)(g_Uh + (size_t)(KF + k2) * NJ + jg + 2) = vi_hi;
    }
}

// ============================ combine (half U, shfl halo) ============================
__device__ __forceinline__ void unpack8(uint2 a, uint2 b, float* d) {
    float2 f;
    f = __half22float2(*(__half2*)&a.x); d[0] = f.x; d[1] = f.y;
    f = __half22float2(*(__half2*)&a.y); d[2] = f.x; d[3] = f.y;
    f = __half22float2(*(__half2*)&b.x); d[4] = f.x; d[5] = f.y;
    f = __half22float2(*(__half2*)&b.y); d[6] = f.x; d[7] = f.y;
}

__global__ void __launch_bounds__(128) combine5_kernel(float* __restrict__ out) {
    __shared__ float sfr[4][2][128];
    __shared__ float sfi[4][2][128];
    const int bc   = blockIdx.z;
    const int lane = threadIdx.x;
    const int ty   = threadIdx.y;
    const int tbase = blockIdx.x * 128;
    const int kb   = (blockIdx.y * 4 + ty) * 32;
    if (kb > 1024) return;

    const int t4  = tbase + lane * 4;
    const int tt4 = (t4 <= 512) ? t4 : 512;
    const size_t jj = (size_t)bc * NSEG + tt4;
    const long baseT = (long)bc * KF;

    float pXr0[4], pXr1[4], pXi0[4], pXi1[4];
#pragma unroll
    for (int e = 0; e < 4; ++e) { pXr0[e] = pXr1[e] = pXi0[e] = pXi1[e] = 0.f; }

#pragma unroll 2
    for (int i = 0; i < 34; ++i) {
        int k = kb - 1 + i;
        int kk = k;
        float sgn = 1.f;
        if (kk < 0)         { kk = -kk;       sgn = -1.f; }
        else if (kk > 1024) { kk = 2048 - kk; sgn = -1.f; }

        const __half* pr = g_Uh + (size_t)kk * NJ + jj;
        const __half* pi = g_Uh + (size_t)(KF + kk) * NJ + jj;
        uint2 vr_ = *(const uint2*)pr;
        uint2 vi_ = *(const uint2*)pi;
        uint2 vrn, vin;
        vrn.x = __shfl_down_sync(0xffffffffu, vr_.x, 1);
        vrn.y = __shfl_down_sync(0xffffffffu, vr_.y, 1);
        vin.x = __shfl_down_sync(0xffffffffu, vi_.x, 1);
        vin.y = __shfl_down_sync(0xffffffffu, vi_.y, 1);
        if (lane == 31) {
            vrn = *(const uint2*)(pr + 4);
            vin = *(const uint2*)(pi + 4);
        }
        float rr[8], ii[8];
        unpack8(vr_, vrn, rr);
        unpack8(vi_, vin, ii);

        float xr[4], xi[4];
        switch (kk & 3) {
            case 0:
#pragma unroll
                for (int e = 0; e < 4; ++e) {
                    xr[e] = rr[e] + rr[e+1] + rr[e+2] + rr[e+3];
                    xi[e] = sgn * (ii[e] + ii[e+1] + ii[e+2] + ii[e+3]);
                }
                break;
            case 1:
#pragma unroll
                for (int e = 0; e < 4; ++e) {
                    xr[e] = rr[e] + ii[e+1] - rr[e+2] - ii[e+3];
                    xi[e] = sgn * (ii[e] - rr[e+1] - ii[e+2] + rr[e+3]);
                }
                break;
            case 2:
#pragma unroll
                for (int e = 0; e < 4; ++e) {
                    xr[e] = rr[e] - rr[e+1] + rr[e+2] - rr[e+3];
                    xi[e] = sgn * (ii[e] - ii[e+1] + ii[e+2] - ii[e+3]);
                }
                break;
            default:
#pragma unroll
                for (int e = 0; e < 4; ++e) {
                    xr[e] = rr[e] - ii[e+1] - rr[e+2] + ii[e+3];
                    xi[e] = sgn * (ii[e] + rr[e+1] - ii[e+2] - rr[e+3]);
                }
                break;
        }

        if (i >= 2) {
            const int ko = k - 1;
            const int buf = i & 1;
            float4 vr, vi;
            vr.x = 0.5f * pXr1[0] - 0.25f * (pXr0[0] + xr[0]);
            vr.y = 0.5f * pXr1[1] - 0.25f * (pXr0[1] + xr[1]);
            vr.z = 0.5f * pXr1[2] - 0.25f * (pXr0[2] + xr[2]);
            vr.w = 0.5f * pXr1[3] - 0.25f * (pXr0[3] + xr[3]);
            vi.x = 0.5f * pXi1[0] - 0.25f * (pXi0[0] + xi[0]);
            vi.y = 0.5f * pXi1[1] - 0.25f * (pXi0[1] + xi[1]);
            vi.z = 0.5f * pXi1[2] - 0.25f * (pXi0[2] + xi[2]);
            vi.w = 0.5f * pXi1[3] - 0.25f * (pXi0[3] + xi[3]);
            *(float4*)&sfr[ty][buf][lane * 4] = vr;
            *(float4*)&sfi[ty][buf][lane * 4] = vi;
            __syncwarp();
            if (ko <= 1024) {
                const long baseR = (baseT + ko) * NT;
#pragma unroll
                for (int e = 0; e < 4; ++e) {
                    int t = tbase + 32 * e + lane;
                    if (t <= 512) {
                        out[baseR + t]            = sfr[ty][buf][32 * e + lane];
                        out[IMAG_OFF + baseR + t] = sfi[ty][buf][32 * e + lane];
                    }
                }
            }
        }
#pragma unroll
        for (int e = 0; e < 4; ++e) {
            pXr0[e] = pXr1[e]; pXr1[e] = xr[e];
            pXi0[e] = pXi1[e]; pXi1[e] = xi[e];
        }
    }
}

// ============================ launch ============================
extern "C" void kernel_launch(void* const* d_in, const int* in_sizes, int n_in,
                              void* d_out, int out_size)
{
    const float* x = (const float*)d_in[0];
    float* out = (float*)d_out;

    cudaFuncSetAttribute(gemm_mma_kernel,
                         cudaFuncAttributeMaxDynamicSharedMemorySize, GEMM_SMEM);

    prep_kernel<<<PREP_GRID, 256>>>(x);
    gemm_mma_kernel<<<dim3(NJ / 128, 17), 256, GEMM_SMEM>>>();
    combine5_kernel<<<dim3(5, 9, NBC), dim3(32, 4)>>>(out);
}